// round 2
// baseline (speedup 1.0000x reference)
#include <cuda_runtime.h>
#include <cstdint>

// Problem shape (fixed by the dataset)
#define BB 4
#define LL 2048
#define CC 1024

// Tiling
#define CT 32            // channels per block
#define LP 32            // L elements per piece
#define G  8             // chunk groups per piece
#define EPT (LP / G)     // 4 elements per thread per piece
#define THREADS (CT * G) // 256
#define PIECES (LL / LP) // 64
#define SLOTS 3          // triple buffer

// SMEM layout (floats):
//   buf  : SLOTS * (A: LP*CT*8 + X: LP*CT*8) = 3 * 16384 floats
//   agg  : 16 * G * CT = 4096 floats   ([k][g][c], k=0..7 Acum, 8..15 Ycum)
//   carry: 8 * CT = 256 floats         ([k][c])
#define BUF_FLOATS_PER_SLOT (2 * LP * CT * 8)       // 16384
#define BUF_F4_PER_SLOT     (BUF_FLOATS_PER_SLOT/4) // 4096
#define X_F4_OFF            (LP * CT * 8 / 4)       // 2048 (within slot, f4 units)
#define AGG_OFF_F   (SLOTS * BUF_FLOATS_PER_SLOT)   // 49152
#define CARRY_OFF_F (AGG_OFF_F + 16 * G * CT)       // 53248
#define SMEM_FLOATS (CARRY_OFF_F + 8 * CT)          // 53504
#define SMEM_BYTES  (SMEM_FLOATS * 4)               // 214016

__device__ __forceinline__ void cp_async16(uint32_t saddr, const void* gptr) {
    asm volatile("cp.async.cg.shared.global [%0], [%1], 16;\n" :: "r"(saddr), "l"(gptr));
}

// R = P @ Q (+ Init), all 2x2 complex matrices as float[8] laid out [i][j][re/im]
__device__ __forceinline__ void cmm(const float* P, const float* Q, const float* I, float* R) {
#pragma unroll
    for (int i = 0; i < 2; i++) {
#pragma unroll
        for (int j = 0; j < 2; j++) {
            float re, im;
            if (I) { re = I[(i * 2 + j) * 2]; im = I[(i * 2 + j) * 2 + 1]; }
            else   { re = 0.f; im = 0.f; }
#pragma unroll
            for (int k = 0; k < 2; k++) {
                const float pr = P[(i * 2 + k) * 2], pi = P[(i * 2 + k) * 2 + 1];
                const float qr = Q[(k * 2 + j) * 2], qi = Q[(k * 2 + j) * 2 + 1];
                re = fmaf(pr, qr, re); re = fmaf(-pi, qi, re);
                im = fmaf(pr, qi, im); im = fmaf(pi, qr, im);
            }
            R[(i * 2 + j) * 2] = re;
            R[(i * 2 + j) * 2 + 1] = im;
        }
    }
}

__device__ __forceinline__ void ld_mat(const float4* buf4, int q, float* m) {
    float4 a = buf4[q], b = buf4[q + 1];
    m[0] = a.x; m[1] = a.y; m[2] = a.z; m[3] = a.w;
    m[4] = b.x; m[5] = b.y; m[6] = b.z; m[7] = b.w;
}

__global__ void __launch_bounds__(THREADS, 1)
pscan_kernel(const float* __restrict__ Ag, const float* __restrict__ Xg,
             float* __restrict__ Yg) {
    extern __shared__ float smem[];
    float4* buf4 = (float4*)smem;
    float* sAgg = smem + AGG_OFF_F;
    float* sCarry = smem + CARRY_OFF_F;

    const int tid = threadIdx.x;
    const int c = tid & (CT - 1);   // channel lane
    const int g = tid >> 5;         // chunk group
    const int b = blockIdx.y;
    const int c0 = blockIdx.x * CT;

    const float4* A4 = (const float4*)Ag;
    const float4* X4 = (const float4*)Xg;
    float4* Y4 = (float4*)Yg;

    // zero the carry
    if (tid < 8 * CT) sCarry[tid] = 0.f;

    // ---- prefetch piece 0 ----
    {
        const int gbase = ((b * LL + 0 * LP) * CC + c0) * 2; // float4 units
        uint32_t sbase = (uint32_t)__cvta_generic_to_shared(&buf4[0]);
#pragma unroll
        for (int j = 0; j < 8; j++) {
            int q = tid + j * THREADS;
            int lr = q >> 6, rem = q & 63;
            int gidx = gbase + lr * (CC * 2) + rem;
            cp_async16(sbase + q * 16, &A4[gidx]);
            cp_async16(sbase + (X_F4_OFF + q) * 16, &X4[gidx]);
        }
        asm volatile("cp.async.commit_group;\n");
    }

    for (int p = 0; p < PIECES; ++p) {
        const int slot = p % SLOTS;

        // ---- prefetch piece p+1 ----
        if (p + 1 < PIECES) {
            const int pn = p + 1, sn = pn % SLOTS;
            const int gbase = ((b * LL + pn * LP) * CC + c0) * 2;
            uint32_t sbase = (uint32_t)__cvta_generic_to_shared(&buf4[sn * BUF_F4_PER_SLOT]);
#pragma unroll
            for (int j = 0; j < 8; j++) {
                int q = tid + j * THREADS;
                int lr = q >> 6, rem = q & 63;
                int gidx = gbase + lr * (CC * 2) + rem;
                cp_async16(sbase + q * 16, &A4[gidx]);
                cp_async16(sbase + (X_F4_OFF + q) * 16, &X4[gidx]);
            }
            asm volatile("cp.async.commit_group;\n");
        } else {
            asm volatile("cp.async.commit_group;\n"); // empty group keeps counts aligned
        }

        asm volatile("cp.async.wait_group 1;\n");
        __syncthreads();   // B1: piece p resident; prev replay finished

        const int sb = slot * BUF_F4_PER_SLOT;

        // ---- per-thread serial aggregate over EPT elements ----
        float Acum[8], Ycum[8];
        {
            int lr = g * EPT;
            int q = sb + (lr * CT + c) * 2;
            ld_mat(buf4, q, Acum);
            ld_mat(buf4, q + X_F4_OFF, Ycum);
        }
#pragma unroll
        for (int i = 1; i < EPT; i++) {
            float Ae[8], Xe[8], T[8];
            int lr = g * EPT + i;
            int q = sb + (lr * CT + c) * 2;
            ld_mat(buf4, q, Ae);
            ld_mat(buf4, q + X_F4_OFF, Xe);
            cmm(Ae, Acum, nullptr, T);
#pragma unroll
            for (int k = 0; k < 8; k++) Acum[k] = T[k];
            cmm(Ae, Ycum, Xe, T);
#pragma unroll
            for (int k = 0; k < 8; k++) Ycum[k] = T[k];
        }
#pragma unroll
        for (int k = 0; k < 8; k++) {
            sAgg[k * (G * CT) + g * CT + c] = Acum[k];
            sAgg[(8 + k) * (G * CT) + g * CT + c] = Ycum[k];
        }
        __syncthreads();   // B2: aggregates visible

        // ---- exclusive prefix for this chunk (serial over earlier groups) ----
        float Yp[8];
#pragma unroll
        for (int k = 0; k < 8; k++) Yp[k] = sCarry[k * CT + c];
        for (int gp = 0; gp < g; gp++) {
            float Am[8], Xm[8], T[8];
#pragma unroll
            for (int k = 0; k < 8; k++) {
                Am[k] = sAgg[k * (G * CT) + gp * CT + c];
                Xm[k] = sAgg[(8 + k) * (G * CT) + gp * CT + c];
            }
            cmm(Am, Yp, Xm, T);
#pragma unroll
            for (int k = 0; k < 8; k++) Yp[k] = T[k];
        }
        __syncthreads();   // B3: everyone done reading agg + carry

        // ---- replay with carry, write output ----
        float Y[8];
#pragma unroll
        for (int k = 0; k < 8; k++) Y[k] = Yp[k];
#pragma unroll
        for (int i = 0; i < EPT; i++) {
            float Ae[8], Xe[8], T[8];
            int lr = g * EPT + i;
            int q = sb + (lr * CT + c) * 2;
            ld_mat(buf4, q, Ae);
            ld_mat(buf4, q + X_F4_OFF, Xe);
            cmm(Ae, Y, Xe, T);
#pragma unroll
            for (int k = 0; k < 8; k++) Y[k] = T[k];
            int l = p * LP + lr;
            int oidx = ((b * LL + l) * CC + c0 + c) * 2;
            __stcs(&Y4[oidx],     make_float4(Y[0], Y[1], Y[2], Y[3]));
            __stcs(&Y4[oidx + 1], make_float4(Y[4], Y[5], Y[6], Y[7]));
        }
        if (g == G - 1) {
#pragma unroll
            for (int k = 0; k < 8; k++) sCarry[k * CT + c] = Y[k];
        }
        // next iteration's B1 orders carry write before its readers
    }
}

extern "C" void kernel_launch(void* const* d_in, const int* in_sizes, int n_in,
                              void* d_out, int out_size) {
    const float* A = (const float*)d_in[0];
    const float* X = (const float*)d_in[1];
    float* Y = (float*)d_out;

    cudaFuncSetAttribute(pscan_kernel, cudaFuncAttributeMaxDynamicSharedMemorySize,
                         SMEM_BYTES);

    dim3 grid(CC / CT, BB);
    pscan_kernel<<<grid, THREADS, SMEM_BYTES>>>(A, X, Y);
}

// round 8
// speedup vs baseline: 1.1427x; 1.1427x over previous
#include <cuda_runtime.h>
#include <cstdint>

// Problem shape (fixed by the dataset)
#define BB 4
#define LL 2048
#define CC 1024

// Tiling
#define CT 8             // channels per block
#define LP 32            // L elements per piece
#define G  8             // chunk groups per piece
#define EPT (LP / G)     // 4 elements per thread per piece
#define THREADS (CT * G) // 64
#define PIECES (LL / LP) // 64
#define SLOTS 3          // triple buffer

// SMEM layout (floats):
//   buf  : SLOTS * (A: LP*CT*8 + X: LP*CT*8) = 3 * 4096 floats
//   agg  : G*CT*16 = 1024 floats   ([g][c][k], k=0..7 Acum, 8..15 Ycum)
//   carry: 2 * CT * 8 = 128 floats ([buf][c][k], ping-pong)
#define BUF_FLOATS_PER_SLOT (2 * LP * CT * 8)       // 4096
#define BUF_F4_PER_SLOT     (BUF_FLOATS_PER_SLOT/4) // 1024
#define X_F4_OFF            (LP * CT * 8 / 4)       // 512 (within slot, f4 units)
#define ROW_F4              (CT * 8 / 4)            // 16 f4 per L-row
#define AGG_OFF_F   (SLOTS * BUF_FLOATS_PER_SLOT)   // 12288
#define CARRY_OFF_F (AGG_OFF_F + G * CT * 16)       // 13312
#define SMEM_FLOATS (CARRY_OFF_F + 2 * CT * 8)      // 13440
#define SMEM_BYTES  (SMEM_FLOATS * 4)               // 53760

__device__ __forceinline__ void cp_async16(uint32_t saddr, const void* gptr) {
    asm volatile("cp.async.cg.shared.global [%0], [%1], 16;\n" :: "r"(saddr), "l"(gptr));
}

// R = P @ Q (+ Init), all 2x2 complex matrices as float[8] laid out [i][j][re/im]
__device__ __forceinline__ void cmm(const float* P, const float* Q, const float* I, float* R) {
#pragma unroll
    for (int i = 0; i < 2; i++) {
#pragma unroll
        for (int j = 0; j < 2; j++) {
            float re, im;
            if (I) { re = I[(i * 2 + j) * 2]; im = I[(i * 2 + j) * 2 + 1]; }
            else   { re = 0.f; im = 0.f; }
#pragma unroll
            for (int k = 0; k < 2; k++) {
                const float pr = P[(i * 2 + k) * 2], pi = P[(i * 2 + k) * 2 + 1];
                const float qr = Q[(k * 2 + j) * 2], qi = Q[(k * 2 + j) * 2 + 1];
                re = fmaf(pr, qr, re); re = fmaf(-pi, qi, re);
                im = fmaf(pr, qi, im); im = fmaf(pi, qr, im);
            }
            R[(i * 2 + j) * 2] = re;
            R[(i * 2 + j) * 2 + 1] = im;
        }
    }
}

__device__ __forceinline__ void ld_mat(const float4* buf4, int q, float* m) {
    float4 a = buf4[q], b = buf4[q + 1];
    m[0] = a.x; m[1] = a.y; m[2] = a.z; m[3] = a.w;
    m[4] = b.x; m[5] = b.y; m[6] = b.z; m[7] = b.w;
}

__global__ void __launch_bounds__(THREADS)
pscan_kernel(const float* __restrict__ Ag, const float* __restrict__ Xg,
             float* __restrict__ Yg) {
    extern __shared__ float smem[];
    float4* buf4 = (float4*)smem;
    float* sAgg = smem + AGG_OFF_F;
    float* sCarry = smem + CARRY_OFF_F;

    const int tid = threadIdx.x;
    const int c = tid & (CT - 1);   // channel lane
    const int g = tid >> 3;         // chunk group
    const int b = blockIdx.y;
    const int c0 = blockIdx.x * CT;

    const float4* A4 = (const float4*)Ag;
    const float4* X4 = (const float4*)Xg;
    float4* Y4 = (float4*)Yg;

    // zero carry buffer 0 (read by piece 0)
    if (tid < CT * 8) sCarry[tid] = 0.f;

    // ---- prefetch piece 0 into slot 0 ----
    {
        const int gbase = ((b * LL + 0) * CC + c0) * 2; // float4 units
        uint32_t sbase = (uint32_t)__cvta_generic_to_shared(&buf4[0]);
#pragma unroll
        for (int j = 0; j < 8; j++) {
            int q = tid + j * THREADS;          // 0..511
            int lr = q / ROW_F4, rem = q % ROW_F4;
            int gidx = gbase + lr * (CC * 2) + rem;
            cp_async16(sbase + q * 16, &A4[gidx]);
            cp_async16(sbase + (X_F4_OFF + q) * 16, &X4[gidx]);
        }
        asm volatile("cp.async.commit_group;\n");
    }

    for (int p = 0; p < PIECES; ++p) {
        const int slot = p % SLOTS;

        // ---- prefetch piece p+1 ----
        if (p + 1 < PIECES) {
            const int pn = p + 1, sn = pn % SLOTS;
            const int gbase = ((b * LL + pn * LP) * CC + c0) * 2;
            uint32_t sbase = (uint32_t)__cvta_generic_to_shared(&buf4[sn * BUF_F4_PER_SLOT]);
#pragma unroll
            for (int j = 0; j < 8; j++) {
                int q = tid + j * THREADS;
                int lr = q / ROW_F4, rem = q % ROW_F4;
                int gidx = gbase + lr * (CC * 2) + rem;
                cp_async16(sbase + q * 16, &A4[gidx]);
                cp_async16(sbase + (X_F4_OFF + q) * 16, &X4[gidx]);
            }
            asm volatile("cp.async.commit_group;\n");
        } else {
            asm volatile("cp.async.commit_group;\n"); // empty group keeps counts aligned
        }

        asm volatile("cp.async.wait_group 1;\n");
        __syncthreads();   // B1: piece p resident in slot; prior-phase smem reads done

        const int sb = slot * BUF_F4_PER_SLOT;

        // ---- load this thread's EPT elements into registers ----
        float Am[EPT][8], Xm[EPT][8];
#pragma unroll
        for (int i = 0; i < EPT; i++) {
            const int lr = g * EPT + i;
            const int q = sb + (lr * CT + c) * 2;
            ld_mat(buf4, q, Am[i]);
            ld_mat(buf4, q + X_F4_OFF, Xm[i]);
        }

        // ---- per-thread serial aggregate over EPT elements ----
        float Acum[8], Ycum[8];
#pragma unroll
        for (int k = 0; k < 8; k++) { Acum[k] = Am[0][k]; Ycum[k] = Xm[0][k]; }
#pragma unroll
        for (int i = 1; i < EPT; i++) {
            float T[8];
            cmm(Am[i], Acum, nullptr, T);
#pragma unroll
            for (int k = 0; k < 8; k++) Acum[k] = T[k];
            cmm(Am[i], Ycum, Xm[i], T);
#pragma unroll
            for (int k = 0; k < 8; k++) Ycum[k] = T[k];
        }
        {
            float4* dst = (float4*)(sAgg + (g * CT + c) * 16);
            dst[0] = make_float4(Acum[0], Acum[1], Acum[2], Acum[3]);
            dst[1] = make_float4(Acum[4], Acum[5], Acum[6], Acum[7]);
            dst[2] = make_float4(Ycum[0], Ycum[1], Ycum[2], Ycum[3]);
            dst[3] = make_float4(Ycum[4], Ycum[5], Ycum[6], Ycum[7]);
        }
        __syncthreads();   // B2: aggregates visible

        // ---- exclusive prefix for this chunk (serial over earlier groups) ----
        float Yp[8];
        {
            const float4* cb = (const float4*)(sCarry + (p & 1) * (CT * 8) + c * 8);
            float4 c1 = cb[0], c2 = cb[1];
            Yp[0] = c1.x; Yp[1] = c1.y; Yp[2] = c1.z; Yp[3] = c1.w;
            Yp[4] = c2.x; Yp[5] = c2.y; Yp[6] = c2.z; Yp[7] = c2.w;
        }
        for (int gp = 0; gp < g; gp++) {
            float Amm[8], Xmm[8], T[8];
            const float4* src = (const float4*)(sAgg + (gp * CT + c) * 16);
            float4 v0 = src[0], v1 = src[1], v2 = src[2], v3 = src[3];
            Amm[0] = v0.x; Amm[1] = v0.y; Amm[2] = v0.z; Amm[3] = v0.w;
            Amm[4] = v1.x; Amm[5] = v1.y; Amm[6] = v1.z; Amm[7] = v1.w;
            Xmm[0] = v2.x; Xmm[1] = v2.y; Xmm[2] = v2.z; Xmm[3] = v2.w;
            Xmm[4] = v3.x; Xmm[5] = v3.y; Xmm[6] = v3.z; Xmm[7] = v3.w;
            cmm(Amm, Yp, Xmm, T);
#pragma unroll
            for (int k = 0; k < 8; k++) Yp[k] = T[k];
        }

        // ---- replay with carry (from registers), write output ----
        float Y[8];
#pragma unroll
        for (int k = 0; k < 8; k++) Y[k] = Yp[k];
#pragma unroll
        for (int i = 0; i < EPT; i++) {
            float T[8];
            cmm(Am[i], Y, Xm[i], T);
#pragma unroll
            for (int k = 0; k < 8; k++) Y[k] = T[k];
            const int l = p * LP + g * EPT + i;
            const int oidx = ((b * LL + l) * CC + c0 + c) * 2;
            __stcs(&Y4[oidx],     make_float4(Y[0], Y[1], Y[2], Y[3]));
            __stcs(&Y4[oidx + 1], make_float4(Y[4], Y[5], Y[6], Y[7]));
        }
        if (g == G - 1) {
            // ping-pong carry: written for piece p+1, read there after its B1+B2
            float4* cb = (float4*)(sCarry + ((p + 1) & 1) * (CT * 8) + c * 8);
            cb[0] = make_float4(Y[0], Y[1], Y[2], Y[3]);
            cb[1] = make_float4(Y[4], Y[5], Y[6], Y[7]);
        }
        // next iteration's B1 orders carry write before its readers
    }
}

extern "C" void kernel_launch(void* const* d_in, const int* in_sizes, int n_in,
                              void* d_out, int out_size) {
    const float* A = (const float*)d_in[0];
    const float* X = (const float*)d_in[1];
    float* Y = (float*)d_out;

    cudaFuncSetAttribute(pscan_kernel, cudaFuncAttributeMaxDynamicSharedMemorySize,
                         SMEM_BYTES);

    dim3 grid(CC / CT, BB);
    pscan_kernel<<<grid, THREADS, SMEM_BYTES>>>(A, X, Y);
}

// round 9
// speedup vs baseline: 1.1496x; 1.0061x over previous
#include <cuda_runtime.h>
#include <cstdint>

// Problem shape (fixed by the dataset)
#define BB 4
#define LL 2048
#define CC 1024

// Tiling: one warp per block, warp = G groups x CT channels
#define CT 4             // channels per block (lanes c = lane & 3)
#define G  8             // chunk groups (lanes g = lane >> 2)
#define EPT 4            // L elements per thread per piece
#define LP (G * EPT)     // 32 L elements per piece
#define THREADS (CT * G) // 32 (one warp)
#define PIECES (LL / LP) // 64

#define FULLMASK 0xffffffffu

// R = P @ Q (+ I), 2x2 complex matrices as float[8], layout [i][j][re/im]
__device__ __forceinline__ void cmm(const float* P, const float* Q, const float* I, float* R) {
#pragma unroll
    for (int i = 0; i < 2; i++) {
#pragma unroll
        for (int j = 0; j < 2; j++) {
            float re, im;
            if (I) { re = I[(i * 2 + j) * 2]; im = I[(i * 2 + j) * 2 + 1]; }
            else   { re = 0.f; im = 0.f; }
#pragma unroll
            for (int k = 0; k < 2; k++) {
                const float pr = P[(i * 2 + k) * 2], pi = P[(i * 2 + k) * 2 + 1];
                const float qr = Q[(k * 2 + j) * 2], qi = Q[(k * 2 + j) * 2 + 1];
                re = fmaf(pr, qr, re); re = fmaf(-pi, qi, re);
                im = fmaf(pr, qi, im); im = fmaf(pi, qr, im);
            }
            R[(i * 2 + j) * 2] = re;
            R[(i * 2 + j) * 2 + 1] = im;
        }
    }
}

__device__ __forceinline__ void cp8(const float* s, float* d) {
#pragma unroll
    for (int k = 0; k < 8; k++) d[k] = s[k];
}

__global__ void __launch_bounds__(THREADS)
pscan_kernel(const float* __restrict__ Ag, const float* __restrict__ Xg,
             float* __restrict__ Yg) {
    const int lane = threadIdx.x;
    const int c = lane & (CT - 1);
    const int g = lane >> 2;
    const int b = blockIdx.y;
    const int c0 = blockIdx.x * CT;

    const float4* __restrict__ A4 = (const float4*)Ag;
    const float4* __restrict__ X4 = (const float4*)Xg;
    float4* __restrict__ Y4 = (float4*)Yg;

    const int chan2 = (c0 + c) * 2;  // f4 offset of this lane's channel within an L-row

    float carry[8];
#pragma unroll
    for (int k = 0; k < 8; k++) carry[k] = 0.f;

#pragma unroll 1
    for (int p = 0; p < PIECES; ++p) {
        const int l0 = p * LP + g * EPT;

        // ---- direct coalesced loads: 16 independent LDG.128 (streaming) ----
        float Am[EPT][8], Xm[EPT][8];
#pragma unroll
        for (int i = 0; i < EPT; i++) {
            const int idx = (b * LL + l0 + i) * (CC * 2) + chan2;
            float4 a0 = __ldcs(&A4[idx]);
            float4 a1 = __ldcs(&A4[idx + 1]);
            float4 x0 = __ldcs(&X4[idx]);
            float4 x1 = __ldcs(&X4[idx + 1]);
            Am[i][0] = a0.x; Am[i][1] = a0.y; Am[i][2] = a0.z; Am[i][3] = a0.w;
            Am[i][4] = a1.x; Am[i][5] = a1.y; Am[i][6] = a1.z; Am[i][7] = a1.w;
            Xm[i][0] = x0.x; Xm[i][1] = x0.y; Xm[i][2] = x0.z; Xm[i][3] = x0.w;
            Xm[i][4] = x1.x; Xm[i][5] = x1.y; Xm[i][6] = x1.z; Xm[i][7] = x1.w;
        }

        // ---- per-thread serial aggregate over EPT elements ----
        float IA[8], IX[8];
        cp8(Am[0], IA); cp8(Xm[0], IX);
#pragma unroll
        for (int i = 1; i < EPT; i++) {
            float TA[8], TX[8];
            cmm(Am[i], IA, nullptr, TA);    // A_i @ IA
            cmm(Am[i], IX, Xm[i], TX);      // A_i @ IX + X_i
            cp8(TA, IA); cp8(TX, IX);
        }

        // ---- inclusive Kogge-Stone scan over the G groups (shuffle-based) ----
#pragma unroll
        for (int d = 1; d < G; d <<= 1) {
            float tA[8], tX[8];
#pragma unroll
            for (int k = 0; k < 8; k++) {
                tA[k] = __shfl_up_sync(FULLMASK, IA[k], d * CT);
                tX[k] = __shfl_up_sync(FULLMASK, IX[k], d * CT);
            }
            if (g >= d) {
                float nA[8], nX[8];
                cmm(IA, tA, nullptr, nA);   // A_later @ A_earlier
                cmm(IA, tX, IX, nX);        // A_later @ X_earlier + X_later
                cp8(nA, IA); cp8(nX, IX);
            }
        }

        // ---- exclusive prefix (from lane g-1) and full-piece aggregate (lane G-1) ----
        float EA[8], EX[8], FA[8], FX[8];
#pragma unroll
        for (int k = 0; k < 8; k++) {
            EA[k] = __shfl_up_sync(FULLMASK, IA[k], CT);
            EX[k] = __shfl_up_sync(FULLMASK, IX[k], CT);
            FA[k] = __shfl_sync(FULLMASK, IA[k], (G - 1) * CT + c);
            FX[k] = __shfl_sync(FULLMASK, IX[k], (G - 1) * CT + c);
        }

        // start value for this group's replay (uses OLD carry)
        float Yp[8];
        if (g == 0) {
            cp8(carry, Yp);
        } else {
            cmm(EA, carry, EX, Yp);         // A_{0..g-1} @ carry + X_{0..g-1}
        }

        // next piece's carry (uses OLD carry) — every lane computes it for its c
        {
            float nc[8];
            cmm(FA, carry, FX, nc);         // A_{0..G-1} @ carry + X_{0..G-1}
            cp8(nc, carry);
        }

        // ---- replay with carry (all from registers), coalesced streaming stores ----
        float Y[8];
        cp8(Yp, Y);
#pragma unroll
        for (int i = 0; i < EPT; i++) {
            float T[8];
            cmm(Am[i], Y, Xm[i], T);
            cp8(T, Y);
            const int idx = (b * LL + l0 + i) * (CC * 2) + chan2;
            __stcs(&Y4[idx],     make_float4(Y[0], Y[1], Y[2], Y[3]));
            __stcs(&Y4[idx + 1], make_float4(Y[4], Y[5], Y[6], Y[7]));
        }
    }
}

extern "C" void kernel_launch(void* const* d_in, const int* in_sizes, int n_in,
                              void* d_out, int out_size) {
    const float* A = (const float*)d_in[0];
    const float* X = (const float*)d_in[1];
    float* Y = (float*)d_out;

    dim3 grid(CC / CT, BB);   // 256 x 4 = 1024 one-warp CTAs
    pscan_kernel<<<grid, THREADS>>>(A, X, Y);
}